// round 3
// baseline (speedup 1.0000x reference)
#include <cuda_runtime.h>

// Graph_Learn: S[n,i,j] = exp(relu(sum_f |xm[n,i,f]-xm[n,j,f]|*a[f])) / colsum_i
// N=8, T=8 (slice t=4), V=512, F=64. Output (8,512,512) fp32.
// Packed-f32x2 mainloop: per feature 0.5 ADD2 + 1 LOP3 + 0.5 FFMA2.

#define NB   8
#define TB   8
#define VB   512
#define FB   64
#define JT   32       // j-columns per block
#define NTHR 512
#define IGR  16       // i-groups = NTHR/32

typedef unsigned long long ull;

// smem layout (floats): xm[512*64] | ev[512*32] | ps[16*32] | sa[64]
#define SM_E      (VB*FB)
#define SM_PS     (SM_E + VB*JT)
#define SM_A      (SM_PS + IGR*JT)
#define SM_FLOATS (SM_A + FB)

__device__ __forceinline__ ull addx2(ull a, ull b) {
    ull r; asm("add.rn.f32x2 %0, %1, %2;" : "=l"(r) : "l"(a), "l"(b)); return r;
}
__device__ __forceinline__ ull fmax2k(ull a, ull b, ull c) {
    ull r; asm("fma.rn.f32x2 %0, %1, %2, %3;" : "=l"(r) : "l"(a), "l"(b), "l"(c)); return r;
}
__device__ __forceinline__ ull packf2(float lo, float hi) {
    ull r; asm("mov.b64 %0, {%1, %2};" : "=l"(r) : "f"(lo), "f"(hi)); return r;
}
__device__ __forceinline__ float sum2(ull a) {
    float lo, hi; asm("mov.b64 {%0, %1}, %2;" : "=f"(lo), "=f"(hi) : "l"(a)); return lo + hi;
}

__global__ __launch_bounds__(NTHR, 1)
void graph_learn_kernel(const float* __restrict__ x,
                        const float* __restrict__ a,
                        float* __restrict__ out) {
    extern __shared__ float sm[];
    float* xm = sm;            // [512][64]
    float* ev = sm + SM_E;     // [512][32]
    float* ps = sm + SM_PS;    // [16][32]
    float* sa = sm + SM_A;     // [64]

    const int n   = blockIdx.y;
    const int jc  = blockIdx.x;
    const int tid = threadIdx.x;
    const int jl  = tid & 31;     // j-lane within warp
    const int ig  = tid >> 5;     // i-group 0..15

    // cooperative load of the middle time slice xm[n] (128 KB), float4
    const float4* __restrict__ xn4 =
        (const float4*)(x + ((size_t)n * TB + TB / 2) * VB * FB);
    float4* xm4 = (float4*)xm;
    for (int k = tid; k < VB * FB / 4; k += NTHR) xm4[k] = xn4[k];
    // a[64] into smem (broadcast-reloaded in the mainloop)
    if (tid < FB / 4) ((float4*)sa)[tid] = ((const float4*)a)[tid];
    __syncthreads();

    // per-thread j-row, negated and packed to f32x2 (32 ULL regs)
    const int j = jc * JT + jl;
    ull xjn[FB / 2];
    {
        const float4* jr = (const float4*)(xm + j * FB);
        #pragma unroll
        for (int k = 0; k < FB / 4; k++) {
            float4 v = jr[k];
            xjn[2*k]   = packf2(-v.x, -v.y);
            xjn[2*k+1] = packf2(-v.z, -v.w);
        }
    }

    const ull ABSM = 0x7FFFFFFF7FFFFFFFULL;
    const float4* sa4 = (const float4*)sa;
    float csum = 0.f;

    // mainloop: 2 i-rows per iteration, 4 packed accumulator chains
    #pragma unroll 1
    for (int it = 0; it < VB / (2 * IGR); it++) {   // 16 iters
        const int i0 = it * (2 * IGR) + ig;
        const int i1 = i0 + IGR;
        const float4* r0 = (const float4*)(xm + i0 * FB);  // warp-uniform -> broadcast
        const float4* r1 = (const float4*)(xm + i1 * FB);
        ull a00 = 0, a01 = 0, a10 = 0, a11 = 0;
        #pragma unroll
        for (int k = 0; k < FB / 4; k++) {
            float4 av = sa4[k];
            float4 v0 = r0[k];
            float4 v1 = r1[k];
            ull avlo = packf2(av.x, av.y), avhi = packf2(av.z, av.w);
            ull d;
            d = addx2(packf2(v0.x, v0.y), xjn[2*k])     & ABSM; a00 = fmax2k(d, avlo, a00);
            d = addx2(packf2(v0.z, v0.w), xjn[2*k+1])   & ABSM; a01 = fmax2k(d, avhi, a01);
            d = addx2(packf2(v1.x, v1.y), xjn[2*k])     & ABSM; a10 = fmax2k(d, avlo, a10);
            d = addx2(packf2(v1.z, v1.w), xjn[2*k+1])   & ABSM; a11 = fmax2k(d, avhi, a11);
        }
        float s0 = sum2(a00) + sum2(a01);
        float s1 = sum2(a10) + sum2(a11);
        float e0 = __expf(fmaxf(s0, 0.f));
        float e1 = __expf(fmaxf(s1, 0.f));
        ev[i0 * JT + jl] = e0;
        ev[i1 * JT + jl] = e1;
        csum += e0 + e1;
    }

    // column-sum reduction across the 16 i-groups
    ps[ig * JT + jl] = csum;
    __syncthreads();
    float tot = 0.f;
    #pragma unroll
    for (int g = 0; g < IGR; g++) tot += ps[g * JT + jl];
    const float inv = 1.0f / tot;

    // normalize + store (coalesced: warp writes 32 consecutive j)
    float* __restrict__ outn = out + (size_t)n * VB * VB;
    #pragma unroll 1
    for (int m = 0; m < VB / IGR; m++) {
        int ii = m * IGR + ig;
        outn[(size_t)ii * VB + j] = ev[ii * JT + jl] * inv;
    }
}

extern "C" void kernel_launch(void* const* d_in, const int* in_sizes, int n_in,
                              void* d_out, int out_size) {
    const float* x = (const float*)d_in[0];   // (8,8,512,64) fp32
    const float* a = (const float*)d_in[1];   // (64,1) fp32
    float* out = (float*)d_out;               // (8,512,512) fp32

    const int smem_bytes = SM_FLOATS * (int)sizeof(float);  // ~194 KB
    cudaFuncSetAttribute(graph_learn_kernel,
                         cudaFuncAttributeMaxDynamicSharedMemorySize, smem_bytes);

    dim3 grid(VB / JT, NB);   // (16, 8) = 128 blocks, one wave
    graph_learn_kernel<<<grid, NTHR, smem_bytes>>>(x, a, out);
}

// round 4
// speedup vs baseline: 1.3651x; 1.3651x over previous
#include <cuda_runtime.h>

// Graph_Learn: S[n,i,j] = exp(relu(sum_f |xm[n,i,f]-xm[n,j,f]|*a[f])) / colsum_i
// N=8, T=8 (slice t=4), V=512, F=64. Output (8,512,512) fp32.
// Two-phase: (A) symmetric tile scores -> exp into d_out (both orientations),
//            (B) column-sum + normalize in-place.

#define NB   8
#define TB   8
#define VB   512
#define FB   64
#define TS   64            // tile size (i and j)
#define NT   (VB / TS)     // 8 tiles per axis
#define NPAIR (NT * (NT + 1) / 2)   // 36 upper-tri tile pairs

typedef unsigned long long ull;

__device__ __forceinline__ ull addx2(ull a, ull b) {
    ull r; asm("add.rn.f32x2 %0, %1, %2;" : "=l"(r) : "l"(a), "l"(b)); return r;
}
__device__ __forceinline__ ull fmax2k(ull a, ull b, ull c) {
    ull r; asm("fma.rn.f32x2 %0, %1, %2, %3;" : "=l"(r) : "l"(a), "l"(b), "l"(c)); return r;
}
__device__ __forceinline__ ull packf2(float lo, float hi) {
    ull r; asm("mov.b64 %0, {%1, %2};" : "=l"(r) : "f"(lo), "f"(hi)); return r;
}
__device__ __forceinline__ float sum2(ull a) {
    float lo, hi; asm("mov.b64 {%0, %1}, %2;" : "=f"(lo), "=f"(hi) : "l"(a)); return lo + hi;
}

// smem (floats): xi[64][64] | xj[64][64] | ev[64][65] | sa[64]
#define SMA_XJ  (TS * FB)
#define SMA_EV  (2 * TS * FB)
#define SMA_A   (SMA_EV + TS * 65)
#define SMA_FLOATS (SMA_A + FB)

__global__ __launch_bounds__(256, 2)
void score_kernel(const float* __restrict__ x,
                  const float* __restrict__ a,
                  float* __restrict__ out) {
    extern __shared__ float sm[];
    float* xi = sm;                 // [64][64]
    float* xj = sm + SMA_XJ;        // [64][64]
    float* ev = sm + SMA_EV;        // [64][65] padded
    float* sa = sm + SMA_A;         // [64]

    const int n   = blockIdx.y;
    const int tid = threadIdx.x;

    // decode upper-tri tile pair (ti <= tj)
    int ti = 0, rem = blockIdx.x;
    while (rem >= NT - ti) { rem -= NT - ti; ti++; }
    const int tj = ti + rem;

    // tiles are contiguous 16 KB chunks of the middle time slice
    const float* xbase = x + ((size_t)n * TB + TB / 2) * VB * FB;
    {
        const float4* si = (const float4*)(xbase + ti * TS * FB);
        const float4* sj = (const float4*)(xbase + tj * TS * FB);
        float4* xi4 = (float4*)xi;
        float4* xj4 = (float4*)xj;
        for (int k = tid; k < TS * FB / 4; k += 256) { xi4[k] = si[k]; xj4[k] = sj[k]; }
        if (tid < FB / 4) ((float4*)sa)[tid] = ((const float4*)a)[tid];
    }
    __syncthreads();

    const int jl = tid & (TS - 1);   // j within tile (0..63)
    const int ig = tid >> 6;         // i-group (0..3)

    // -xj row packed into registers (32 ull)
    ull xjn[FB / 2];
    {
        const float* jr = xj + jl * FB;
        #pragma unroll
        for (int k = 0; k < FB / 2; k++) xjn[k] = packf2(-jr[2*k], -jr[2*k+1]);
    }

    const ull ABSM = 0x7FFFFFFF7FFFFFFFULL;
    const ulonglong2* sa2 = (const ulonglong2*)sa;

    // mainloop: 2 i-rows per iter, 4 packed accumulator chains.
    // All smem operands read as packed 64/128-bit -> no repack MOVs.
    #pragma unroll 1
    for (int it = 0; it < TS / 8; it++) {        // 8 iters
        const int i0 = (it * 4 + ig) * 2;        // warp-uniform
        const int i1 = i0 + 1;
        const ulonglong2* r0 = (const ulonglong2*)(xi + i0 * FB);
        const ulonglong2* r1 = (const ulonglong2*)(xi + i1 * FB);
        ull a00 = 0, a01 = 0, a10 = 0, a11 = 0;
        #pragma unroll
        for (int k = 0; k < FB / 4; k++) {
            ulonglong2 av = sa2[k];
            ulonglong2 v0 = r0[k];
            ulonglong2 v1 = r1[k];
            ull d;
            d = addx2(v0.x, xjn[2*k])   & ABSM; a00 = fmax2k(d, av.x, a00);
            d = addx2(v0.y, xjn[2*k+1]) & ABSM; a01 = fmax2k(d, av.y, a01);
            d = addx2(v1.x, xjn[2*k])   & ABSM; a10 = fmax2k(d, av.x, a10);
            d = addx2(v1.y, xjn[2*k+1]) & ABSM; a11 = fmax2k(d, av.y, a11);
        }
        float s0 = sum2(a00) + sum2(a01);
        float s1 = sum2(a10) + sum2(a11);
        ev[i0 * 65 + jl] = __expf(fmaxf(s0, 0.f));
        ev[i1 * 65 + jl] = __expf(fmaxf(s1, 0.f));
    }
    __syncthreads();

    float* o = out + (size_t)n * VB * VB;

    // direct tile write: out[ti*64+ir][tj*64+jl]  (coalesced)
    #pragma unroll 1
    for (int m = 0; m < TS / 4; m++) {
        int ir = m * 4 + ig;
        o[(size_t)(ti * TS + ir) * VB + tj * TS + jl] = ev[ir * 65 + jl];
    }

    // transposed tile write: out[tj*64+jr][ti*64+il]  (coalesced via smem)
    if (ti != tj) {
        const int il = tid & (TS - 1);
        const int jg = tid >> 6;
        #pragma unroll 1
        for (int m = 0; m < TS / 4; m++) {
            int jr = m * 4 + jg;
            o[(size_t)(tj * TS + jr) * VB + ti * TS + il] = ev[il * 65 + jr];
        }
    }
}

// Phase B: colsum over i, then scale. Values kept in registers between passes.
__global__ __launch_bounds__(512, 1)
void norm_kernel(float* __restrict__ out) {
    __shared__ float ps[16][32];
    const int tid = threadIdx.x;
    const int jl  = tid & 31;
    const int ig  = tid >> 5;      // 0..15
    float* o = out + (size_t)blockIdx.y * VB * VB + blockIdx.x * 32 + jl;

    float vals[VB / 16];
    float acc = 0.f;
    #pragma unroll
    for (int m = 0; m < VB / 16; m++) {       // 32 i per thread
        vals[m] = o[(size_t)(m * 16 + ig) * VB];
        acc += vals[m];
    }
    ps[ig][jl] = acc;
    __syncthreads();
    float tot = 0.f;
    #pragma unroll
    for (int g = 0; g < 16; g++) tot += ps[g][jl];
    const float inv = 1.0f / tot;
    #pragma unroll
    for (int m = 0; m < VB / 16; m++) {
        o[(size_t)(m * 16 + ig) * VB] = vals[m] * inv;
    }
}

extern "C" void kernel_launch(void* const* d_in, const int* in_sizes, int n_in,
                              void* d_out, int out_size) {
    const float* x = (const float*)d_in[0];   // (8,8,512,64) fp32
    const float* a = (const float*)d_in[1];   // (64,1) fp32
    float* out = (float*)d_out;               // (8,512,512) fp32

    const int smem_bytes = SMA_FLOATS * (int)sizeof(float);  // ~49.7 KB
    cudaFuncSetAttribute(score_kernel,
                         cudaFuncAttributeMaxDynamicSharedMemorySize, smem_bytes);

    dim3 gridA(NPAIR, NB);     // (36, 8) = 288 blocks
    score_kernel<<<gridA, 256, smem_bytes>>>(x, a, out);

    dim3 gridB(VB / 32, NB);   // (16, 8) = 128 blocks
    norm_kernel<<<gridB, 512>>>(out);
}